// round 10
// baseline (speedup 1.0000x reference)
#include <cuda_runtime.h>
#include <cstdint>

// ---------------- problem constants ----------------
#define NROWS   8192
#define KDIM    4096
#define ODIM    4096
#define KW      (KDIM / 32)        // 128 words of packed sign bits per row
#define TW      128                // output tile: 128 x 128
#define CHUNK   16                 // k-words per pipeline stage (= compressor group)
#define KITC    (KW / CHUNK)       // 8 chunks
#define XST_WORDS (2 * CHUNK * TW)              // A + B: 4096 words = 16KB
#define SMEM_BYTES  (4 * XST_WORDS * 4)         // 65536

// ---------------- device scratch (allocation-free rule) ----------------
__device__ __align__(1024) uint32_t g_xT[(size_t)KW * NROWS];
__device__ __align__(1024) uint32_t g_wT[(size_t)KW * ODIM];

// ---------------- helpers ----------------
__device__ __forceinline__ uint32_t smem_u32(const void* p) {
    uint32_t a;
    asm("{ .reg .u64 t; cvta.to.shared.u64 t, %1; cvt.u32.u64 %0, t; }" : "=r"(a) : "l"(p));
    return a;
}
#define CP_ASYNC16(dst, src) \
    asm volatile("cp.async.cg.shared.global [%0], [%1], 16;" :: "r"(dst), "l"(src))
#define CP_COMMIT() asm volatile("cp.async.commit_group;" ::: "memory")
#define CP_WAIT3()  asm volatile("cp.async.wait_group 3;"  ::: "memory")

__device__ __forceinline__ uint32_t xor3(uint32_t a, uint32_t b, uint32_t c) {
    uint32_t d; asm("lop3.b32 %0, %1, %2, %3, 0x96;" : "=r"(d) : "r"(a), "r"(b), "r"(c));
    return d;
}
__device__ __forceinline__ uint32_t maj3(uint32_t a, uint32_t b, uint32_t c) {
    uint32_t d; asm("lop3.b32 %0, %1, %2, %3, 0xE8;" : "=r"(d) : "r"(a), "r"(b), "r"(c));
    return d;
}
__device__ __forceinline__ int imad(int a, int b, int c) {
    int d; asm("mad.lo.s32 %0, %1, %2, %3;" : "=r"(d) : "r"(a), "r"(b), "r"(c));
    return d;
}

// ---------------- pack: f32 -> 1 bit sign, transposed [kw][row] ---------
__global__ void __launch_bounds__(256) pack_bits(const float4* __restrict__ in,
                                                 uint32_t* __restrict__ outT,
                                                 int nShift) {
    const int idx = blockIdx.x * 256 + threadIdx.x;
    const int n   = idx & ((1 << nShift) - 1);
    const int kw  = idx >> nShift;
    const float4* p = in + (size_t)n * (KDIM / 4) + kw * 8;
    uint32_t w = 0;
    #pragma unroll
    for (int j = 0; j < 8; j++) {
        float4 v = p[j];
        w |= (__float_as_uint(v.x) >> 31) << (4 * j);
        w |= (__float_as_uint(v.y) >> 31) << (4 * j + 1);
        w |= (__float_as_uint(v.z) >> 31) << (4 * j + 2);
        w |= (__float_as_uint(v.w) >> 31) << (4 * j + 3);
    }
    outT[idx] = w;
}

// ---------------- XNOR GEMM with 16:5 Wallace compression ----------------
// out[n][o] = 4096 - 2 * sum_kw popc(xT[kw][n] ^ wT[kw][o]) + bias[o]
__global__ void __launch_bounds__(256, 2) xnor_gemm(
    const uint32_t* __restrict__ xT, const uint32_t* __restrict__ wT,
    const float* __restrict__ bias, float* __restrict__ out)
{
    extern __shared__ __align__(16) uint32_t sm[];
    const uint32_t smBase = smem_u32(sm);
    const int tid = threadIdx.x;
    const int tx  = tid & 15;        // 16 col groups
    const int ty  = tid >> 4;        // 16 row groups
    const int mt  = blockIdx.x & 63;
    const int nt  = blockIdx.x >> 6;
    const int mBase = mt * TW;
    const int nBase = nt * TW;

    auto load_stage = [&](int s, int c) {
        #pragma unroll
        for (int k = 0; k < 4; k++) {
            const int ch  = tid + k * 256;
            const int tsr = ch >> 9;
            const int rem = ch & 511;
            const int kw  = rem >> 5;
            const int nq  = rem & 31;
            const uint32_t* gsrc = tsr
                ? (wT + (size_t)(c * CHUNK + kw) * ODIM  + nBase + nq * 4)
                : (xT + (size_t)(c * CHUNK + kw) * NROWS + mBase + nq * 4);
            const uint32_t dst = smBase +
                (uint32_t)((s * XST_WORDS + tsr * 2048 + kw * TW + nq * 4) * 4);
            CP_ASYNC16(dst, gsrc);
        }
    };

    // u16x2 accumulators: [row][colpair], lo = even col, hi = odd col (max 4096)
    uint32_t accP[8][4];
    #pragma unroll
    for (int r = 0; r < 8; r++)
        #pragma unroll
        for (int c = 0; c < 4; c++) accP[r][c] = 0;

    #pragma unroll
    for (int s = 0; s < 3; s++) { load_stage(s, s); CP_COMMIT(); }

    #pragma unroll 1
    for (int c = 0; c < KITC; c++) {
        const int cl = c + 3;
        if (cl < KITC) load_stage(cl & 3, cl);
        CP_COMMIT();
        CP_WAIT3();
        __syncthreads();

        const uint32_t* As = sm + (c & 3) * XST_WORDS;
        const uint32_t* Bs = As + 2048;

        #pragma unroll 1
        for (int cp = 0; cp < 4; cp++) {             // column pairs
            uint32_t Bf[16][2];
            #pragma unroll
            for (int k = 0; k < 16; k++) {
                uint2 u = *reinterpret_cast<const uint2*>(Bs + k * TW + tx * 8 + cp * 2);
                Bf[k][0] = u.x; Bf[k][1] = u.y;
            }
            #pragma unroll
            for (int r = 0; r < 8; r++) {
                uint32_t Af[16];
                #pragma unroll
                for (int k = 0; k < 16; k++)         // tx-independent -> broadcast LDS
                    Af[k] = As[k * TW + ty * 8 + r];

                int tt[2];
                #pragma unroll
                for (int h = 0; h < 2; h++) {
                    uint32_t x[16];
                    #pragma unroll
                    for (int k = 0; k < 16; k++) x[k] = Af[k] ^ Bf[k][h];
                    // Wallace 16 -> planes of weight 1,2,4,8,16
                    const uint32_t s0 = xor3(x[0],  x[1],  x[2]);
                    const uint32_t c0 = maj3(x[0],  x[1],  x[2]);
                    const uint32_t s1 = xor3(x[3],  x[4],  x[5]);
                    const uint32_t c1 = maj3(x[3],  x[4],  x[5]);
                    const uint32_t s2 = xor3(x[6],  x[7],  x[8]);
                    const uint32_t c2 = maj3(x[6],  x[7],  x[8]);
                    const uint32_t s3 = xor3(x[9],  x[10], x[11]);
                    const uint32_t c3 = maj3(x[9],  x[10], x[11]);
                    const uint32_t s4 = xor3(x[12], x[13], x[14]);
                    const uint32_t c4 = maj3(x[12], x[13], x[14]);
                    const uint32_t s5 = xor3(s0, s1, s2);
                    const uint32_t c5 = maj3(s0, s1, s2);
                    const uint32_t s6 = xor3(s3, s4, x[15]);
                    const uint32_t c6 = maj3(s3, s4, x[15]);
                    const uint32_t P1 = s5 ^ s6;
                    const uint32_t c7 = s5 & s6;
                    const uint32_t t0 = xor3(c0, c1, c2);
                    const uint32_t d0 = maj3(c0, c1, c2);
                    const uint32_t t1 = xor3(c3, c4, c5);
                    const uint32_t d1 = maj3(c3, c4, c5);
                    const uint32_t t2 = xor3(t0, t1, c6);
                    const uint32_t d2 = maj3(t0, t1, c6);
                    const uint32_t P2 = t2 ^ c7;
                    const uint32_t d3 = t2 & c7;
                    const uint32_t t3 = xor3(d0, d1, d2);
                    const uint32_t e0 = maj3(d0, d1, d2);
                    const uint32_t P4 = t3 ^ d3;
                    const uint32_t e1 = t3 & d3;
                    const uint32_t P8  = e0 ^ e1;
                    const uint32_t P16 = e0 & e1;
                    int t = __popc(P1);
                    t = imad(__popc(P2),  2,  t);
                    t = imad(__popc(P4),  4,  t);
                    t = imad(__popc(P8),  8,  t);
                    t = imad(__popc(P16), 16, t);
                    tt[h] = t;
                }
                accP[r][cp] = (uint32_t)imad(tt[1], 65536, (int)accP[r][cp] + tt[0]);
            }
        }
        __syncthreads();
    }

    // -------- epilogue: out = 4096 - 2*count + bias --------
    const int rb = mBase + ty * 8;
    const int cb = nBase + tx * 8;
    const float4 bias0 = *reinterpret_cast<const float4*>(bias + cb);
    const float4 bias1 = *reinterpret_cast<const float4*>(bias + cb + 4);

    #pragma unroll
    for (int r = 0; r < 8; r++) {
        const int c0 = (int)(accP[r][0] & 0xFFFF), c1 = (int)(accP[r][0] >> 16);
        const int c2 = (int)(accP[r][1] & 0xFFFF), c3 = (int)(accP[r][1] >> 16);
        const int c4 = (int)(accP[r][2] & 0xFFFF), c5 = (int)(accP[r][2] >> 16);
        const int c6 = (int)(accP[r][3] & 0xFFFF), c7 = (int)(accP[r][3] >> 16);
        float4 o0, o1;
        o0.x = (float)(KDIM - 2 * c0) + bias0.x;
        o0.y = (float)(KDIM - 2 * c1) + bias0.y;
        o0.z = (float)(KDIM - 2 * c2) + bias0.z;
        o0.w = (float)(KDIM - 2 * c3) + bias0.w;
        o1.x = (float)(KDIM - 2 * c4) + bias1.x;
        o1.y = (float)(KDIM - 2 * c5) + bias1.y;
        o1.z = (float)(KDIM - 2 * c6) + bias1.z;
        o1.w = (float)(KDIM - 2 * c7) + bias1.w;
        float* po = out + (size_t)(rb + r) * ODIM + cb;
        *reinterpret_cast<float4*>(po)     = o0;
        *reinterpret_cast<float4*>(po + 4) = o1;
    }
}

// ---------------- host ----------------
extern "C" void kernel_launch(void* const* d_in, const int* in_sizes, int n_in,
                              void* d_out, int out_size) {
    const float* x    = (const float*)d_in[0];
    const float* w    = (const float*)d_in[1];
    const float* bias = (const float*)d_in[2];
    float* out = (float*)d_out;

    void* pxT = nullptr; cudaGetSymbolAddress(&pxT, g_xT);
    void* pwT = nullptr; cudaGetSymbolAddress(&pwT, g_wT);

    pack_bits<<<(KW * NROWS) / 256, 256>>>((const float4*)x, (uint32_t*)pxT, 13);
    pack_bits<<<(KW * ODIM) / 256, 256>>>((const float4*)w, (uint32_t*)pwT, 12);

    cudaFuncSetAttribute(xnor_gemm, cudaFuncAttributeMaxDynamicSharedMemorySize, SMEM_BYTES);

    const int grid = (NROWS / TW) * (ODIM / TW);   // 2048
    xnor_gemm<<<grid, 256, SMEM_BYTES>>>((const uint32_t*)pxT, (const uint32_t*)pwT,
                                         bias, out);
}

// round 11
// speedup vs baseline: 1.3755x; 1.3755x over previous
#include <cuda_runtime.h>
#include <cstdint>

// ---------------- problem constants ----------------
#define NROWS   8192
#define KDIM    4096
#define ODIM    4096
#define KW      (KDIM / 32)        // 128 words of packed sign bits per row
#define TW      128                // output tile: 128 x 128
#define CHUNK   16                 // k-words per pipeline stage
#define KITC    (KW / CHUNK)       // 8 chunks
#define XST_WORDS (2 * CHUNK * TW)              // A + B: 4096 words = 16KB
#define SMEM_BYTES  (4 * XST_WORDS * 4)         // 65536

// ---------------- device scratch (allocation-free rule) ----------------
__device__ __align__(1024) uint32_t g_xT[(size_t)KW * NROWS];
__device__ __align__(1024) uint32_t g_wT[(size_t)KW * ODIM];

// ---------------- helpers ----------------
__device__ __forceinline__ uint32_t smem_u32(const void* p) {
    uint32_t a;
    asm("{ .reg .u64 t; cvta.to.shared.u64 t, %1; cvt.u32.u64 %0, t; }" : "=r"(a) : "l"(p));
    return a;
}
#define CP_ASYNC16(dst, src) \
    asm volatile("cp.async.cg.shared.global [%0], [%1], 16;" :: "r"(dst), "l"(src))
#define CP_COMMIT() asm volatile("cp.async.commit_group;" ::: "memory")
#define CP_WAIT3()  asm volatile("cp.async.wait_group 3;"  ::: "memory")

__device__ __forceinline__ uint32_t xor3(uint32_t a, uint32_t b, uint32_t c) {
    uint32_t d; asm("lop3.b32 %0, %1, %2, %3, 0x96;" : "=r"(d) : "r"(a), "r"(b), "r"(c));
    return d;
}
__device__ __forceinline__ uint32_t maj3(uint32_t a, uint32_t b, uint32_t c) {
    uint32_t d; asm("lop3.b32 %0, %1, %2, %3, 0xE8;" : "=r"(d) : "r"(a), "r"(b), "r"(c));
    return d;
}

// ---------------- pack: f32 -> 1 bit sign, transposed [kw][row] ---------
__global__ void __launch_bounds__(256) pack_bits(const float4* __restrict__ in,
                                                 uint32_t* __restrict__ outT,
                                                 int nShift) {
    const int idx = blockIdx.x * 256 + threadIdx.x;
    const int n   = idx & ((1 << nShift) - 1);
    const int kw  = idx >> nShift;
    const float4* p = in + (size_t)n * (KDIM / 4) + kw * 8;
    uint32_t w = 0;
    #pragma unroll
    for (int j = 0; j < 8; j++) {
        float4 v = p[j];
        w |= (__float_as_uint(v.x) >> 31) << (4 * j);
        w |= (__float_as_uint(v.y) >> 31) << (4 * j + 1);
        w |= (__float_as_uint(v.z) >> 31) << (4 * j + 2);
        w |= (__float_as_uint(v.w) >> 31) << (4 * j + 3);
    }
    outT[idx] = w;
}

// -------- XNOR GEMM: CSA 8->4, u16x2 accumulators, 2 CTAs/SM ----------
// out[n][o] = 4096 - 2 * sum_kw popc(xT[kw][n] ^ wT[kw][o]) + bias[o]
__global__ void __launch_bounds__(256, 2) xnor_gemm(
    const uint32_t* __restrict__ xT, const uint32_t* __restrict__ wT,
    const float* __restrict__ bias, float* __restrict__ out)
{
    extern __shared__ __align__(16) uint32_t sm[];
    const uint32_t smBase = smem_u32(sm);
    const int tid = threadIdx.x;
    const int tx  = tid & 15;        // 16 col groups
    const int ty  = tid >> 4;        // 16 row groups
    const int mt  = blockIdx.x & 63;
    const int nt  = blockIdx.x >> 6;
    const int mBase = mt * TW;
    const int nBase = nt * TW;

    auto load_stage = [&](int s, int c) {
        #pragma unroll
        for (int k = 0; k < 4; k++) {
            const int ch  = tid + k * 256;
            const int tsr = ch >> 9;
            const int rem = ch & 511;
            const int kw  = rem >> 5;
            const int nq  = rem & 31;
            const uint32_t* gsrc = tsr
                ? (wT + (size_t)(c * CHUNK + kw) * ODIM  + nBase + nq * 4)
                : (xT + (size_t)(c * CHUNK + kw) * NROWS + mBase + nq * 4);
            const uint32_t dst = smBase +
                (uint32_t)((s * XST_WORDS + tsr * 2048 + kw * TW + nq * 4) * 4);
            CP_ASYNC16(dst, gsrc);
        }
    };

    // packed u16x2 accumulators: [row][colpair] (counts <= 4096 fit u16)
    uint32_t accP[8][4];
    #pragma unroll
    for (int r = 0; r < 8; r++)
        #pragma unroll
        for (int c = 0; c < 4; c++) accP[r][c] = 0;

    #pragma unroll
    for (int s = 0; s < 3; s++) { load_stage(s, s); CP_COMMIT(); }

    #pragma unroll 1
    for (int c = 0; c < KITC; c++) {
        const int cl = c + 3;
        if (cl < KITC) load_stage(cl & 3, cl);
        CP_COMMIT();
        CP_WAIT3();
        __syncthreads();

        const uint32_t* As = sm + (c & 3) * XST_WORDS;
        const uint32_t* Bs = As + 2048;

        #pragma unroll
        for (int g = 0; g < 2; g++) {
            const int kb = g * 8;
            #pragma unroll
            for (int ch2 = 0; ch2 < 2; ch2++) {     // column halves (4 cols)
                uint32_t Bf[8][4];
                #pragma unroll
                for (int k = 0; k < 8; k++) {
                    uint4 u = *reinterpret_cast<const uint4*>(
                        Bs + (kb + k) * TW + tx * 8 + ch2 * 4);
                    Bf[k][0] = u.x; Bf[k][1] = u.y; Bf[k][2] = u.z; Bf[k][3] = u.w;
                }
                #pragma unroll
                for (int rq = 0; rq < 4; rq++) {    // row quarters (2 rows)
                    uint32_t Af[8][2];
                    #pragma unroll
                    for (int k = 0; k < 8; k++) {
                        uint2 u = *reinterpret_cast<const uint2*>(
                            As + (kb + k) * TW + ty * 8 + rq * 2);
                        Af[k][0] = u.x; Af[k][1] = u.y;
                    }
                    #pragma unroll
                    for (int r = 0; r < 2; r++) {
                        #pragma unroll
                        for (int cp = 0; cp < 2; cp++) {
                            uint32_t tt[2];
                            #pragma unroll
                            for (int h = 0; h < 2; h++) {
                                const int cc = cp * 2 + h;
                                const uint32_t x0 = Af[0][r] ^ Bf[0][cc];
                                const uint32_t x1 = Af[1][r] ^ Bf[1][cc];
                                const uint32_t x2 = Af[2][r] ^ Bf[2][cc];
                                const uint32_t x3 = Af[3][r] ^ Bf[3][cc];
                                const uint32_t x4 = Af[4][r] ^ Bf[4][cc];
                                const uint32_t x5 = Af[5][r] ^ Bf[5][cc];
                                const uint32_t x6 = Af[6][r] ^ Bf[6][cc];
                                const uint32_t x7 = Af[7][r] ^ Bf[7][cc];
                                const uint32_t s0 = xor3(x0, x1, x2);
                                const uint32_t c0 = maj3(x0, x1, x2);
                                const uint32_t s1 = xor3(x3, x4, x5);
                                const uint32_t c1 = maj3(x3, x4, x5);
                                const uint32_t s2 = x6 ^ x7;
                                const uint32_t c2 = x6 & x7;
                                const uint32_t S  = xor3(s0, s1, s2);
                                const uint32_t C3 = maj3(s0, s1, s2);
                                const uint32_t S2 = xor3(c0, c1, c2);
                                const uint32_t C2 = maj3(c0, c1, c2);
                                tt[h] = __popc(S)
                                      + 2 * (__popc(S2) + __popc(C3))
                                      + 4 * __popc(C2);
                            }
                            accP[rq * 2 + r][ch2 * 2 + cp] += tt[0] + (tt[1] << 16);
                        }
                    }
                }
            }
        }
        __syncthreads();
    }

    // -------- epilogue: out = 4096 - 2*count + bias --------
    const int rb = mBase + ty * 8;
    const int cb = nBase + tx * 8;
    const float4 bias0 = *reinterpret_cast<const float4*>(bias + cb);
    const float4 bias1 = *reinterpret_cast<const float4*>(bias + cb + 4);

    #pragma unroll
    for (int r = 0; r < 8; r++) {
        const int c0 = (int)(accP[r][0] & 0xFFFF), c1 = (int)(accP[r][0] >> 16);
        const int c2 = (int)(accP[r][1] & 0xFFFF), c3 = (int)(accP[r][1] >> 16);
        const int c4 = (int)(accP[r][2] & 0xFFFF), c5 = (int)(accP[r][2] >> 16);
        const int c6 = (int)(accP[r][3] & 0xFFFF), c7 = (int)(accP[r][3] >> 16);
        float4 o0, o1;
        o0.x = (float)(KDIM - 2 * c0) + bias0.x;
        o0.y = (float)(KDIM - 2 * c1) + bias0.y;
        o0.z = (float)(KDIM - 2 * c2) + bias0.z;
        o0.w = (float)(KDIM - 2 * c3) + bias0.w;
        o1.x = (float)(KDIM - 2 * c4) + bias1.x;
        o1.y = (float)(KDIM - 2 * c5) + bias1.y;
        o1.z = (float)(KDIM - 2 * c6) + bias1.z;
        o1.w = (float)(KDIM - 2 * c7) + bias1.w;
        float* po = out + (size_t)(rb + r) * ODIM + cb;
        *reinterpret_cast<float4*>(po)     = o0;
        *reinterpret_cast<float4*>(po + 4) = o1;
    }
}

// ---------------- host ----------------
extern "C" void kernel_launch(void* const* d_in, const int* in_sizes, int n_in,
                              void* d_out, int out_size) {
    const float* x    = (const float*)d_in[0];
    const float* w    = (const float*)d_in[1];
    const float* bias = (const float*)d_in[2];
    float* out = (float*)d_out;

    void* pxT = nullptr; cudaGetSymbolAddress(&pxT, g_xT);
    void* pwT = nullptr; cudaGetSymbolAddress(&pwT, g_wT);

    pack_bits<<<(KW * NROWS) / 256, 256>>>((const float4*)x, (uint32_t*)pxT, 13);
    pack_bits<<<(KW * ODIM) / 256, 256>>>((const float4*)w, (uint32_t*)pwT, 12);

    cudaFuncSetAttribute(xnor_gemm, cudaFuncAttributeMaxDynamicSharedMemorySize, SMEM_BYTES);

    const int grid = (NROWS / TW) * (ODIM / TW);   // 2048
    xnor_gemm<<<grid, 256, SMEM_BYTES>>>((const uint32_t*)pxT, (const uint32_t*)pwT,
                                         bias, out);
}